// round 1
// baseline (speedup 1.0000x reference)
#include <cuda_runtime.h>
#include <cstdint>

// EGNN layer: B=2, N=768, D=32, DM=64, K=16
// out = concat(flatten(x_update (B,N,3)), flatten(h_update (B,N,32)))

#define NB 2
#define NN 768
#define DD 32
#define DMC 64
#define KNN 16
#define TJ 128
#define NTILES (NN / TJ)
#define THREADS 256
#define FP 65                    // ftile pitch (bank-conflict-free column reads)

// Per-node precomputed e0 partials (folded with BN affine)
__device__ float g_As[NB * NN * DMC];   // (h_j @ W_top) * s0
__device__ float g_Bs[NB * NN * DMC];   // (h_i @ W_mid + b0) * s0 + t0

// ---------------------------------------------------------------------------
// Kernel 1: per-node e0 factorization
// ---------------------------------------------------------------------------
__global__ void precompute_kernel(const float* __restrict__ h,
                                  const float* __restrict__ e0W,
                                  const float* __restrict__ e0b,
                                  const float* __restrict__ e0s,
                                  const float* __restrict__ e0t) {
    __shared__ float hv[DD];
    const int node = blockIdx.x;          // b*NN + n
    const int c = threadIdx.x;            // 0..63
    if (c < DD) hv[c] = h[node * DD + c];
    __syncthreads();
    float a1 = 0.f, a2 = 0.f;
#pragma unroll
    for (int d = 0; d < DD; d++) {
        const float hh = hv[d];
        a1 = fmaf(hh, e0W[d * DMC + c], a1);
        a2 = fmaf(hh, e0W[(DD + d) * DMC + c], a2);
    }
    const float s = e0s[c];
    g_As[node * DMC + c] = a1 * s;
    g_Bs[node * DMC + c] = (a2 + e0b[c]) * s + e0t[c];
}

// ---------------------------------------------------------------------------
// Main kernel: one CTA per (b, i)
// ---------------------------------------------------------------------------
struct SmemLayout {
    float W1[DMC * DMC];      // folded e1W
    float W2[DMC * DMC];      // folded c0W
    float ftile[TJ * FP];     // f1 -> f2(m_edge) -> g, reused
    float xs[NN * 3];         // x coords of all nodes in batch b
    float d2all[NN];
    float bias1[DMC], bias2[DMC];
    float Bsi[DMC], wds[DMC], c1wf[DMC], mnode[DMC];
    float selval[KNN];
    float xsum[3];
    float redv[8];
    int   redi[8];
    int   seli[KNN];
};

__global__ void __launch_bounds__(THREADS)
egnn_main_kernel(const float* __restrict__ x, const float* __restrict__ h,
                 const float* __restrict__ e0W, const float* __restrict__ e0s,
                 const float* __restrict__ e1W, const float* __restrict__ e1b,
                 const float* __restrict__ e1s, const float* __restrict__ e1t,
                 const float* __restrict__ c0W, const float* __restrict__ c0b,
                 const float* __restrict__ c0s, const float* __restrict__ c0t,
                 const float* __restrict__ c1W, const float* __restrict__ c1b,
                 const float* __restrict__ c1s, const float* __restrict__ c1t,
                 const float* __restrict__ n0W, const float* __restrict__ n0b,
                 const float* __restrict__ n0s, const float* __restrict__ n0t,
                 float* __restrict__ out) {
    extern __shared__ char smraw[];
    SmemLayout* sm = reinterpret_cast<SmemLayout*>(smraw);

    const int bi = blockIdx.x;           // b*NN + i
    const int b  = bi / NN;
    const int i  = bi - b * NN;
    const int t  = threadIdx.x;

    // ---- load + fold weights ----
    for (int e = t; e < DMC * DMC; e += THREADS) {
        const int cc = e & (DMC - 1);
        sm->W1[e] = e1W[e] * e1s[cc];
        sm->W2[e] = c0W[e] * c0s[cc];
    }
    if (t < DMC) {
        sm->bias1[t] = e1b[t] * e1s[t] + e1t[t];
        sm->bias2[t] = c0b[t] * c0s[t] + c0t[t];
        sm->Bsi[t]   = g_Bs[bi * DMC + t];
        sm->wds[t]   = e0W[2 * DD * DMC + t] * e0s[t];   // row 64 of e0W
        sm->c1wf[t]  = c1W[t] * c1s[0];
        sm->mnode[t] = 0.f;
    }
    for (int e = t; e < NN * 3; e += THREADS) sm->xs[e] = x[b * NN * 3 + e];
    if (t == 0) { sm->xsum[0] = 0.f; sm->xsum[1] = 0.f; sm->xsum[2] = 0.f; }
    const float c1bf = c1b[0] * c1s[0] + c1t[0];
    __syncthreads();

    const float xi0 = sm->xs[i * 3 + 0];
    const float xi1 = sm->xs[i * 3 + 1];
    const float xi2 = sm->xs[i * 3 + 2];

    // ---- Phase A: distances ----
    for (int j = t; j < NN; j += THREADS) {
        const float dx = sm->xs[j * 3 + 0] - xi0;
        const float dy = sm->xs[j * 3 + 1] - xi1;
        const float dz = sm->xs[j * 3 + 2] - xi2;
        sm->d2all[j] = dx * dx + dy * dy + dz * dz;
    }
    __syncthreads();

    // ---- KNN selection: 16 sequential block argmins (tie-break lower index) ----
    const float INF = __int_as_float(0x7f800000);
    for (int s = 0; s < KNN; s++) {
        float bv = INF; int bidx = NN;
#pragma unroll
        for (int j = t; j < NN; j += THREADS) {
            const float v = sm->d2all[j];
            if (v < bv || (v == bv && j < bidx)) { bv = v; bidx = j; }
        }
#pragma unroll
        for (int off = 16; off; off >>= 1) {
            const float ov = __shfl_down_sync(0xffffffffu, bv, off);
            const int   oi = __shfl_down_sync(0xffffffffu, bidx, off);
            if (ov < bv || (ov == bv && oi < bidx)) { bv = ov; bidx = oi; }
        }
        if ((t & 31) == 0) { sm->redv[t >> 5] = bv; sm->redi[t >> 5] = bidx; }
        __syncthreads();
        if (t == 0) {
            float fv = sm->redv[0]; int fi = sm->redi[0];
#pragma unroll
            for (int w = 1; w < 8; w++) {
                const float wv = sm->redv[w]; const int wi = sm->redi[w];
                if (wv < fv || (wv == fv && wi < fi)) { fv = wv; fi = wi; }
            }
            sm->seli[s] = fi;
            sm->selval[s] = fv;
            sm->d2all[fi] = INF;                 // mask
        }
        __syncthreads();
    }
    if (t < KNN) sm->d2all[sm->seli[t]] = sm->selval[t];  // restore
    __syncthreads();

    // ---- Phase B: tile loop over j ----
    const int r  = t >> 4;      // 0..15 -> rows 8r..8r+7
    const int cc = t & 15;      // 0..15 -> cols 4cc..4cc+3
    float xacc0 = 0.f, xacc1 = 0.f, xacc2 = 0.f;

    for (int tile = 0; tile < NTILES; tile++) {
        const int j0 = tile * TJ;

        // f1 = relu(As[j] + Bs[i] + d2*wds)
        for (int e = t; e < TJ * DMC; e += THREADS) {
            const int jj = e >> 6, c = e & 63;
            float v = g_As[(b * NN + j0 + jj) * DMC + c] + sm->Bsi[c];
            v = fmaf(sm->d2all[j0 + jj], sm->wds[c], v);
            sm->ftile[jj * FP + c] = fmaxf(v, 0.f);
        }
        __syncthreads();

        // GEMM 1: f2 = relu(f1 @ W1 + bias1)   (128x64x64)
        {
            float acc[8][4];
#pragma unroll
            for (int u = 0; u < 8; u++)
#pragma unroll
                for (int v = 0; v < 4; v++) acc[u][v] = 0.f;
#pragma unroll 4
            for (int k = 0; k < DMC; k++) {
                const float4 wv = *reinterpret_cast<const float4*>(&sm->W1[k * DMC + cc * 4]);
#pragma unroll
                for (int u = 0; u < 8; u++) {
                    const float a = sm->ftile[(r * 8 + u) * FP + k];
                    acc[u][0] = fmaf(a, wv.x, acc[u][0]);
                    acc[u][1] = fmaf(a, wv.y, acc[u][1]);
                    acc[u][2] = fmaf(a, wv.z, acc[u][2]);
                    acc[u][3] = fmaf(a, wv.w, acc[u][3]);
                }
            }
            __syncthreads();
#pragma unroll
            for (int u = 0; u < 8; u++)
#pragma unroll
                for (int v = 0; v < 4; v++)
                    sm->ftile[(r * 8 + u) * FP + cc * 4 + v] =
                        fmaxf(acc[u][v] + sm->bias1[cc * 4 + v], 0.f);
            __syncthreads();
        }

        // m_node accumulation from m_edge (= f2) for selected neighbors in tile
        if (t < DMC) {
            float am = 0.f;
#pragma unroll
            for (int s = 0; s < KNN; s++) {
                const int j = sm->seli[s] - j0;
                if ((unsigned)j < (unsigned)TJ) am += sm->ftile[j * FP + t];
            }
            sm->mnode[t] += am;
        }

        // GEMM 2: g = relu(f2 @ W2 + bias2)
        {
            float acc[8][4];
#pragma unroll
            for (int u = 0; u < 8; u++)
#pragma unroll
                for (int v = 0; v < 4; v++) acc[u][v] = 0.f;
#pragma unroll 4
            for (int k = 0; k < DMC; k++) {
                const float4 wv = *reinterpret_cast<const float4*>(&sm->W2[k * DMC + cc * 4]);
#pragma unroll
                for (int u = 0; u < 8; u++) {
                    const float a = sm->ftile[(r * 8 + u) * FP + k];
                    acc[u][0] = fmaf(a, wv.x, acc[u][0]);
                    acc[u][1] = fmaf(a, wv.y, acc[u][1]);
                    acc[u][2] = fmaf(a, wv.z, acc[u][2]);
                    acc[u][3] = fmaf(a, wv.w, acc[u][3]);
                }
            }
            __syncthreads();
#pragma unroll
            for (int u = 0; u < 8; u++)
#pragma unroll
                for (int v = 0; v < 4; v++)
                    sm->ftile[(r * 8 + u) * FP + cc * 4 + v] =
                        fmaxf(acc[u][v] + sm->bias2[cc * 4 + v], 0.f);
            __syncthreads();
        }

        // c1 head: w[j] = relu(g[j] . c1wf + c1bf); accumulate coord update
        if (t < TJ) {
            float dot = c1bf;
#pragma unroll 8
            for (int c = 0; c < DMC; c++)
                dot = fmaf(sm->ftile[t * FP + c], sm->c1wf[c], dot);
            const float w = fmaxf(dot, 0.f);
            const int j = j0 + t;
            xacc0 = fmaf(w, sm->xs[j * 3 + 0] - xi0, xacc0);
            xacc1 = fmaf(w, sm->xs[j * 3 + 1] - xi1, xacc1);
            xacc2 = fmaf(w, sm->xs[j * 3 + 2] - xi2, xacc2);
        }
        __syncthreads();    // ftile reused next tile
    }

    // ---- reduce coordinate update ----
#pragma unroll
    for (int off = 16; off; off >>= 1) {
        xacc0 += __shfl_down_sync(0xffffffffu, xacc0, off);
        xacc1 += __shfl_down_sync(0xffffffffu, xacc1, off);
        xacc2 += __shfl_down_sync(0xffffffffu, xacc2, off);
    }
    if ((t & 31) == 0) {
        atomicAdd(&sm->xsum[0], xacc0);
        atomicAdd(&sm->xsum[1], xacc1);
        atomicAdd(&sm->xsum[2], xacc2);
    }
    __syncthreads();

    // ---- outputs ----
    if (t < 3) out[bi * 3 + t] = sm->xs[i * 3 + t] + sm->xsum[t];
    if (t < DD) {
        float acc = 0.f;
        const float* hrow = h + bi * DD;
#pragma unroll
        for (int k = 0; k < DD; k++) acc = fmaf(hrow[k], n0W[k * DD + t], acc);
#pragma unroll
        for (int k = 0; k < DMC; k++) acc = fmaf(sm->mnode[k], n0W[(DD + k) * DD + t], acc);
        const float v = (acc + n0b[t]) * n0s[t] + n0t[t];
        out[NB * NN * 3 + bi * DD + t] = fmaxf(v, 0.f);
    }
}

// ---------------------------------------------------------------------------
extern "C" void kernel_launch(void* const* d_in, const int* in_sizes, int n_in,
                              void* d_out, int out_size) {
    const float* x   = (const float*)d_in[0];
    const float* h   = (const float*)d_in[1];
    const float* e0W = (const float*)d_in[2];
    const float* e0b = (const float*)d_in[3];
    const float* e0s = (const float*)d_in[4];
    const float* e0t = (const float*)d_in[5];
    const float* e1W = (const float*)d_in[6];
    const float* e1b = (const float*)d_in[7];
    const float* e1s = (const float*)d_in[8];
    const float* e1t = (const float*)d_in[9];
    const float* c0W = (const float*)d_in[10];
    const float* c0b = (const float*)d_in[11];
    const float* c0s = (const float*)d_in[12];
    const float* c0t = (const float*)d_in[13];
    const float* c1W = (const float*)d_in[14];
    const float* c1b = (const float*)d_in[15];
    const float* c1s = (const float*)d_in[16];
    const float* c1t = (const float*)d_in[17];
    const float* n0W = (const float*)d_in[18];
    const float* n0b = (const float*)d_in[19];
    const float* n0s = (const float*)d_in[20];
    const float* n0t = (const float*)d_in[21];
    float* out = (float*)d_out;

    static_assert(sizeof(SmemLayout) < 200 * 1024, "smem too big");
    cudaFuncSetAttribute(egnn_main_kernel,
                         cudaFuncAttributeMaxDynamicSharedMemorySize,
                         (int)sizeof(SmemLayout));

    precompute_kernel<<<NB * NN, 64>>>(h, e0W, e0b, e0s, e0t);
    egnn_main_kernel<<<NB * NN, THREADS, sizeof(SmemLayout)>>>(
        x, h, e0W, e0s,
        e1W, e1b, e1s, e1t,
        c0W, c0b, c0s, c0t,
        c1W, c1b, c1s, c1t,
        n0W, n0b, n0s, n0t,
        out);
}

// round 2
// speedup vs baseline: 1.1730x; 1.1730x over previous
#include <cuda_runtime.h>
#include <cstdint>

// EGNN layer: B=2, N=768, D=32, DM=64, K=16
// out = concat(flatten(x_update (B,N,3)), flatten(h_update (B,N,32)))

#define NB 2
#define NN 768
#define DD 32
#define DMC 64
#define KNN 16
#define TJ 128
#define NTILES (NN / TJ)
#define THREADS 256
#define FP 68                    // ftile pitch (multiple of 4 for 16B-aligned LDS.128)

typedef unsigned long long ull;

__device__ __forceinline__ void ffma2(ull& d, ull a, ull b) {
    asm("fma.rn.f32x2 %0, %1, %2, %0;" : "+l"(d) : "l"(a), "l"(b));
}
__device__ __forceinline__ ull packf2(float lo, float hi) {
    ull r; asm("mov.b64 %0, {%1, %2};" : "=l"(r) : "f"(lo), "f"(hi)); return r;
}
__device__ __forceinline__ float2 unpackf2(ull v) {
    float2 f; asm("mov.b64 {%0, %1}, %2;" : "=f"(f.x), "=f"(f.y) : "l"(v)); return f;
}

// Per-node precomputed e0 partials (folded with BN affine)
__device__ float g_As[NB * NN * DMC];   // (h_j @ W_top) * s0
__device__ float g_Bs[NB * NN * DMC];   // (h_i @ W_mid + b0) * s0 + t0

// ---------------------------------------------------------------------------
// Kernel 1: per-node e0 factorization
// ---------------------------------------------------------------------------
__global__ void precompute_kernel(const float* __restrict__ h,
                                  const float* __restrict__ e0W,
                                  const float* __restrict__ e0b,
                                  const float* __restrict__ e0s,
                                  const float* __restrict__ e0t) {
    __shared__ float hv[DD];
    const int node = blockIdx.x;          // b*NN + n
    const int c = threadIdx.x;            // 0..63
    if (c < DD) hv[c] = h[node * DD + c];
    __syncthreads();
    float a1 = 0.f, a2 = 0.f;
#pragma unroll
    for (int d = 0; d < DD; d++) {
        const float hh = hv[d];
        a1 = fmaf(hh, e0W[d * DMC + c], a1);
        a2 = fmaf(hh, e0W[(DD + d) * DMC + c], a2);
    }
    const float s = e0s[c];
    g_As[node * DMC + c] = a1 * s;
    g_Bs[node * DMC + c] = (a2 + e0b[c]) * s + e0t[c];
}

// ---------------------------------------------------------------------------
// Main kernel: one CTA per (b, i)
// ---------------------------------------------------------------------------
// Weight smem layout: pair-interleaved + lane-permuted, conflict-free:
//   Wp[p * 64 + (c & 3) * 16 + (c >> 2)] = ( W[2p][c], W[2p+1][c] )  as f32x2 in ull
struct SmemLayout {
    ull   W1p[32 * DMC];      // 16 KB, folded e1W
    ull   W2p[32 * DMC];      // 16 KB, folded c0W
    float ftile[TJ * FP];     // f1 -> f2(m_edge) -> g, reused (16B-aligned rows)
    float xs[NN * 3];         // x coords of all nodes in batch b
    float d2all[NN];
    float bias1[DMC], bias2[DMC];
    float Bsi[DMC], wds[DMC], c1wf[DMC], mnode[DMC];
    float selval[KNN];
    float xsum[3];
    float redv[8];
    int   redi[8];
    int   seli[KNN];
};

// One 128x64x64 GEMM + bias + relu, f32x2 even/odd-k packed math.
// Reads A from sm->ftile, weights from Wp, writes result back to sm->ftile.
__device__ __forceinline__ void gemm_tile(SmemLayout* sm, const ull* __restrict__ Wp,
                                          const float* __restrict__ bias,
                                          int r, int cc) {
    ull acc[8][4];
#pragma unroll
    for (int u = 0; u < 8; u++)
#pragma unroll
        for (int v = 0; v < 4; v++) acc[u][v] = 0ULL;

#pragma unroll 2
    for (int p4 = 0; p4 < DMC / 4; p4++) {       // chunk of 4 k-values
        ull w0[4], w1[4];
#pragma unroll
        for (int v = 0; v < 4; v++) {
            w0[v] = Wp[(2 * p4 + 0) * DMC + v * 16 + cc];   // (k0,k1) pair
            w1[v] = Wp[(2 * p4 + 1) * DMC + v * 16 + cc];   // (k2,k3) pair
        }
#pragma unroll
        for (int u = 0; u < 8; u++) {
            const ulonglong2 aq = *reinterpret_cast<const ulonglong2*>(
                &sm->ftile[(r * 8 + u) * FP + p4 * 4]);
#pragma unroll
            for (int v = 0; v < 4; v++) {
                ffma2(acc[u][v], aq.x, w0[v]);
                ffma2(acc[u][v], aq.y, w1[v]);
            }
        }
    }
    __syncthreads();
    const float b0 = bias[cc * 4 + 0], b1 = bias[cc * 4 + 1];
    const float b2 = bias[cc * 4 + 2], b3 = bias[cc * 4 + 3];
#pragma unroll
    for (int u = 0; u < 8; u++) {
        const float2 a0 = unpackf2(acc[u][0]);
        const float2 a1 = unpackf2(acc[u][1]);
        const float2 a2 = unpackf2(acc[u][2]);
        const float2 a3 = unpackf2(acc[u][3]);
        float4 o;
        o.x = fmaxf(a0.x + a0.y + b0, 0.f);
        o.y = fmaxf(a1.x + a1.y + b1, 0.f);
        o.z = fmaxf(a2.x + a2.y + b2, 0.f);
        o.w = fmaxf(a3.x + a3.y + b3, 0.f);
        *reinterpret_cast<float4*>(&sm->ftile[(r * 8 + u) * FP + cc * 4]) = o;
    }
    __syncthreads();
}

__global__ void __launch_bounds__(THREADS, 2)
egnn_main_kernel(const float* __restrict__ x, const float* __restrict__ h,
                 const float* __restrict__ e0W, const float* __restrict__ e0s,
                 const float* __restrict__ e1W, const float* __restrict__ e1b,
                 const float* __restrict__ e1s, const float* __restrict__ e1t,
                 const float* __restrict__ c0W, const float* __restrict__ c0b,
                 const float* __restrict__ c0s, const float* __restrict__ c0t,
                 const float* __restrict__ c1W, const float* __restrict__ c1b,
                 const float* __restrict__ c1s, const float* __restrict__ c1t,
                 const float* __restrict__ n0W, const float* __restrict__ n0b,
                 const float* __restrict__ n0s, const float* __restrict__ n0t,
                 float* __restrict__ out) {
    extern __shared__ char smraw[];
    SmemLayout* sm = reinterpret_cast<SmemLayout*>(smraw);

    const int bi = blockIdx.x;           // b*NN + i
    const int b  = bi / NN;
    const int i  = bi - b * NN;
    const int t  = threadIdx.x;

    // ---- load + fold weights into pair-interleaved conflict-free layout ----
    for (int e = t; e < 32 * DMC; e += THREADS) {
        const int p = e >> 6;            // k-pair index
        const int c = e & 63;            // output column
        const float s1 = e1s[c], s2 = c0s[c];
        const int dst = p * DMC + (c & 3) * 16 + (c >> 2);
        sm->W1p[dst] = packf2(e1W[(2 * p) * DMC + c] * s1,
                              e1W[(2 * p + 1) * DMC + c] * s1);
        sm->W2p[dst] = packf2(c0W[(2 * p) * DMC + c] * s2,
                              c0W[(2 * p + 1) * DMC + c] * s2);
    }
    if (t < DMC) {
        sm->bias1[t] = e1b[t] * e1s[t] + e1t[t];
        sm->bias2[t] = c0b[t] * c0s[t] + c0t[t];
        sm->Bsi[t]   = g_Bs[bi * DMC + t];
        sm->wds[t]   = e0W[2 * DD * DMC + t] * e0s[t];   // row 64 of e0W
        sm->c1wf[t]  = c1W[t] * c1s[0];
        sm->mnode[t] = 0.f;
    }
    for (int e = t; e < NN * 3; e += THREADS) sm->xs[e] = x[b * NN * 3 + e];
    if (t == 0) { sm->xsum[0] = 0.f; sm->xsum[1] = 0.f; sm->xsum[2] = 0.f; }
    const float c1bf = c1b[0] * c1s[0] + c1t[0];
    __syncthreads();

    const float xi0 = sm->xs[i * 3 + 0];
    const float xi1 = sm->xs[i * 3 + 1];
    const float xi2 = sm->xs[i * 3 + 2];

    // ---- Phase A: distances ----
    for (int j = t; j < NN; j += THREADS) {
        const float dx = sm->xs[j * 3 + 0] - xi0;
        const float dy = sm->xs[j * 3 + 1] - xi1;
        const float dz = sm->xs[j * 3 + 2] - xi2;
        sm->d2all[j] = dx * dx + dy * dy + dz * dz;
    }
    __syncthreads();

    // ---- KNN selection: 16 sequential block argmins (tie-break lower index) ----
    const float INF = __int_as_float(0x7f800000);
    for (int s = 0; s < KNN; s++) {
        float bv = INF; int bidx = NN;
#pragma unroll
        for (int j = t; j < NN; j += THREADS) {
            const float v = sm->d2all[j];
            if (v < bv || (v == bv && j < bidx)) { bv = v; bidx = j; }
        }
#pragma unroll
        for (int off = 16; off; off >>= 1) {
            const float ov = __shfl_down_sync(0xffffffffu, bv, off);
            const int   oi = __shfl_down_sync(0xffffffffu, bidx, off);
            if (ov < bv || (ov == bv && oi < bidx)) { bv = ov; bidx = oi; }
        }
        if ((t & 31) == 0) { sm->redv[t >> 5] = bv; sm->redi[t >> 5] = bidx; }
        __syncthreads();
        if (t == 0) {
            float fv = sm->redv[0]; int fi = sm->redi[0];
#pragma unroll
            for (int w = 1; w < 8; w++) {
                const float wv = sm->redv[w]; const int wi = sm->redi[w];
                if (wv < fv || (wv == fv && wi < fi)) { fv = wv; fi = wi; }
            }
            sm->seli[s] = fi;
            sm->selval[s] = fv;
            sm->d2all[fi] = INF;                 // mask
        }
        __syncthreads();
    }
    if (t < KNN) sm->d2all[sm->seli[t]] = sm->selval[t];  // restore
    __syncthreads();

    // ---- Phase B: tile loop over j ----
    const int r  = t >> 4;      // 0..15 -> rows 8r..8r+7
    const int cc = t & 15;      // 0..15 -> cols 4cc..4cc+3
    float xacc0 = 0.f, xacc1 = 0.f, xacc2 = 0.f;

    for (int tile = 0; tile < NTILES; tile++) {
        const int j0 = tile * TJ;

        // f1 = relu(As[j] + Bs[i] + d2*wds), vectorized float4
        for (int e = t; e < TJ * (DMC / 4); e += THREADS) {
            const int jj = e >> 4, c4 = (e & 15) * 4;
            const float4 As4 = *reinterpret_cast<const float4*>(
                &g_As[(b * NN + j0 + jj) * DMC + c4]);
            const float d2j = sm->d2all[j0 + jj];
            float4 o;
            o.x = fmaxf(fmaf(d2j, sm->wds[c4 + 0], As4.x + sm->Bsi[c4 + 0]), 0.f);
            o.y = fmaxf(fmaf(d2j, sm->wds[c4 + 1], As4.y + sm->Bsi[c4 + 1]), 0.f);
            o.z = fmaxf(fmaf(d2j, sm->wds[c4 + 2], As4.z + sm->Bsi[c4 + 2]), 0.f);
            o.w = fmaxf(fmaf(d2j, sm->wds[c4 + 3], As4.w + sm->Bsi[c4 + 3]), 0.f);
            *reinterpret_cast<float4*>(&sm->ftile[jj * FP + c4]) = o;
        }
        __syncthreads();

        // GEMM 1: f2 = relu(f1 @ W1 + bias1)   (128x64x64)
        gemm_tile(sm, sm->W1p, sm->bias1, r, cc);

        // m_node accumulation from m_edge (= f2) for selected neighbors in tile
        if (t < DMC) {
            float am = 0.f;
#pragma unroll
            for (int s = 0; s < KNN; s++) {
                const int j = sm->seli[s] - j0;
                if ((unsigned)j < (unsigned)TJ) am += sm->ftile[j * FP + t];
            }
            sm->mnode[t] += am;
        }

        // GEMM 2: g = relu(f2 @ W2 + bias2)
        gemm_tile(sm, sm->W2p, sm->bias2, r, cc);

        // c1 head: w[j] = relu(g[j] . c1wf + c1bf); accumulate coord update
        if (t < TJ) {
            float dot = c1bf;
#pragma unroll 8
            for (int c = 0; c < DMC; c++)
                dot = fmaf(sm->ftile[t * FP + c], sm->c1wf[c], dot);
            const float w = fmaxf(dot, 0.f);
            const int j = j0 + t;
            xacc0 = fmaf(w, sm->xs[j * 3 + 0] - xi0, xacc0);
            xacc1 = fmaf(w, sm->xs[j * 3 + 1] - xi1, xacc1);
            xacc2 = fmaf(w, sm->xs[j * 3 + 2] - xi2, xacc2);
        }
        __syncthreads();    // ftile reused next tile
    }

    // ---- reduce coordinate update ----
#pragma unroll
    for (int off = 16; off; off >>= 1) {
        xacc0 += __shfl_down_sync(0xffffffffu, xacc0, off);
        xacc1 += __shfl_down_sync(0xffffffffu, xacc1, off);
        xacc2 += __shfl_down_sync(0xffffffffu, xacc2, off);
    }
    if ((t & 31) == 0) {
        atomicAdd(&sm->xsum[0], xacc0);
        atomicAdd(&sm->xsum[1], xacc1);
        atomicAdd(&sm->xsum[2], xacc2);
    }
    __syncthreads();

    // ---- outputs ----
    if (t < 3) out[bi * 3 + t] = sm->xs[i * 3 + t] + sm->xsum[t];
    if (t < DD) {
        float acc = 0.f;
        const float* hrow = h + bi * DD;
#pragma unroll
        for (int k = 0; k < DD; k++) acc = fmaf(hrow[k], n0W[k * DD + t], acc);
#pragma unroll
        for (int k = 0; k < DMC; k++) acc = fmaf(sm->mnode[k], n0W[(DD + k) * DD + t], acc);
        const float v = (acc + n0b[t]) * n0s[t] + n0t[t];
        out[NB * NN * 3 + bi * DD + t] = fmaxf(v, 0.f);
    }
}

// ---------------------------------------------------------------------------
extern "C" void kernel_launch(void* const* d_in, const int* in_sizes, int n_in,
                              void* d_out, int out_size) {
    const float* x   = (const float*)d_in[0];
    const float* h   = (const float*)d_in[1];
    const float* e0W = (const float*)d_in[2];
    const float* e0b = (const float*)d_in[3];
    const float* e0s = (const float*)d_in[4];
    const float* e0t = (const float*)d_in[5];
    const float* e1W = (const float*)d_in[6];
    const float* e1b = (const float*)d_in[7];
    const float* e1s = (const float*)d_in[8];
    const float* e1t = (const float*)d_in[9];
    const float* c0W = (const float*)d_in[10];
    const float* c0b = (const float*)d_in[11];
    const float* c0s = (const float*)d_in[12];
    const float* c0t = (const float*)d_in[13];
    const float* c1W = (const float*)d_in[14];
    const float* c1b = (const float*)d_in[15];
    const float* c1s = (const float*)d_in[16];
    const float* c1t = (const float*)d_in[17];
    const float* n0W = (const float*)d_in[18];
    const float* n0b = (const float*)d_in[19];
    const float* n0s = (const float*)d_in[20];
    const float* n0t = (const float*)d_in[21];
    float* out = (float*)d_out;

    static_assert(sizeof(SmemLayout) < 110 * 1024, "smem too big");
    cudaFuncSetAttribute(egnn_main_kernel,
                         cudaFuncAttributeMaxDynamicSharedMemorySize,
                         (int)sizeof(SmemLayout));

    precompute_kernel<<<NB * NN, 64>>>(h, e0W, e0b, e0s, e0t);
    egnn_main_kernel<<<NB * NN, THREADS, sizeof(SmemLayout)>>>(
        x, h, e0W, e0s,
        e1W, e1b, e1s, e1t,
        c0W, c0b, c0s, c0t,
        c1W, c1b, c1s, c1t,
        n0W, n0b, n0s, n0t,
        out);
}

// round 5
// speedup vs baseline: 2.9334x; 2.5008x over previous
#include <cuda_runtime.h>
#include <cuda_bf16.h>
#include <cstdint>

// EGNN layer: B=2, N=768, D=32, DM=64, K=16
#define NB 2
#define NN 768
#define DD 32
#define DMC 64
#define KNN 16
#define TJ 128
#define NTILES (NN / TJ)
#define THREADS 256

typedef unsigned int u32;
typedef unsigned long long u64;

// ---- bf16 split helpers ----
__device__ __forceinline__ void splitpair(float v0, float v1, u32& hi, u32& lo) {
    __nv_bfloat162 h = __floats2bfloat162_rn(v0, v1);
    const float l0 = v0 - __low2float(h);
    const float l1 = v1 - __high2float(h);
    __nv_bfloat162 l = __floats2bfloat162_rn(l0, l1);
    hi = *reinterpret_cast<u32*>(&h);
    lo = *reinterpret_cast<u32*>(&l);
}

// m16n8k16 row.col f32.bf16.bf16.f32
__device__ __forceinline__ void mma16816(float* c, const u32* a, u32 b0, u32 b1) {
    asm volatile(
        "mma.sync.aligned.m16n8k16.row.col.f32.bf16.bf16.f32 "
        "{%0,%1,%2,%3}, {%4,%5,%6,%7}, {%8,%9}, {%0,%1,%2,%3};"
        : "+f"(c[0]), "+f"(c[1]), "+f"(c[2]), "+f"(c[3])
        : "r"(a[0]), "r"(a[1]), "r"(a[2]), "r"(a[3]), "r"(b0), "r"(b1));
}

// Per-node precomputed e0 partials (folded with BN affine)
__device__ float g_As[NB * NN * DMC];   // (h_j @ W_top) * s0
__device__ float g_Bs[NB * NN * DMC];   // (h_i @ W_mid + b0) * s0 + t0

__global__ void precompute_kernel(const float* __restrict__ h,
                                  const float* __restrict__ e0W,
                                  const float* __restrict__ e0b,
                                  const float* __restrict__ e0s,
                                  const float* __restrict__ e0t) {
    __shared__ float hv[DD];
    const int node = blockIdx.x;
    const int c = threadIdx.x;
    if (c < DD) hv[c] = h[node * DD + c];
    __syncthreads();
    float a1 = 0.f, a2 = 0.f;
#pragma unroll
    for (int d = 0; d < DD; d++) {
        const float hh = hv[d];
        a1 = fmaf(hh, e0W[d * DMC + c], a1);
        a2 = fmaf(hh, e0W[(DD + d) * DMC + c], a2);
    }
    const float s = e0s[c];
    g_As[node * DMC + c] = a1 * s;
    g_Bs[node * DMC + c] = (a2 + e0b[c]) * s + e0t[c];
}

// ---------------------------------------------------------------------------
// B-fragment smem: per (kstep 0..3, ntile 0..7, lane 0..31) one u64 = {b0, b1}
// where b0 = bf16x2 (k=16ks+2tg, +1 ; n=8nt+g), b1 = same with k+8.
struct SmemLayout {
    u64 B1h[1024], B1l[1024];    // e1W folded, hi/lo  (8KB each)
    u64 B2h[1024], B2l[1024];    // c0W folded, hi/lo
    float xs[NN * 3];
    float d2all[NN];
    float stage[KNN][DMC];       // f2 rows of selected neighbors
    float Bsi[DMC], wds[DMC], bias1[DMC], bias2[DMC], c1wf[DMC], mnode[DMC];
    int   slotmap[NN];
    float selval[KNN];
    float xsum[3];
    float redv[8];
    int   redi[8];
    int   seli[KNN];
};

__global__ void __launch_bounds__(THREADS, 2)
egnn_main_kernel(const float* __restrict__ x, const float* __restrict__ h,
                 const float* __restrict__ e0W, const float* __restrict__ e0s,
                 const float* __restrict__ e1W, const float* __restrict__ e1b,
                 const float* __restrict__ e1s, const float* __restrict__ e1t,
                 const float* __restrict__ c0W, const float* __restrict__ c0b,
                 const float* __restrict__ c0s, const float* __restrict__ c0t,
                 const float* __restrict__ c1W, const float* __restrict__ c1b,
                 const float* __restrict__ c1s, const float* __restrict__ c1t,
                 const float* __restrict__ n0W, const float* __restrict__ n0b,
                 const float* __restrict__ n0s, const float* __restrict__ n0t,
                 float* __restrict__ out) {
    extern __shared__ char smraw[];
    SmemLayout* sm = reinterpret_cast<SmemLayout*>(smraw);

    const int bi = blockIdx.x;
    const int b  = bi / NN;
    const int i  = bi - b * NN;
    const int t  = threadIdx.x;
    const int w  = t >> 5;
    const int lane = t & 31;
    const int g  = lane >> 2;
    const int tg = lane & 3;

    // ---- fold weights into per-lane B-fragment layout ----
    for (int e = t; e < 1024; e += THREADS) {
        const int l  = e & 31;
        const int nt = (e >> 5) & 7;
        const int ks = e >> 8;
        const int k0 = ks * 16 + 2 * (l & 3);
        const int n  = nt * 8 + (l >> 2);
        const float s1 = e1s[n], s2 = c0s[n];
        u32 h0, l0, h1, l1;
        splitpair(e1W[k0 * DMC + n] * s1, e1W[(k0 + 1) * DMC + n] * s1, h0, l0);
        splitpair(e1W[(k0 + 8) * DMC + n] * s1, e1W[(k0 + 9) * DMC + n] * s1, h1, l1);
        sm->B1h[e] = (u64)h0 | ((u64)h1 << 32);
        sm->B1l[e] = (u64)l0 | ((u64)l1 << 32);
        splitpair(c0W[k0 * DMC + n] * s2, c0W[(k0 + 1) * DMC + n] * s2, h0, l0);
        splitpair(c0W[(k0 + 8) * DMC + n] * s2, c0W[(k0 + 9) * DMC + n] * s2, h1, l1);
        sm->B2h[e] = (u64)h0 | ((u64)h1 << 32);
        sm->B2l[e] = (u64)l0 | ((u64)l1 << 32);
    }
    if (t < DMC) {
        sm->bias1[t] = e1b[t] * e1s[t] + e1t[t];
        sm->bias2[t] = c0b[t] * c0s[t] + c0t[t];
        sm->Bsi[t]   = g_Bs[bi * DMC + t];
        sm->wds[t]   = e0W[2 * DD * DMC + t] * e0s[t];
        sm->c1wf[t]  = c1W[t] * c1s[0];
    }
    for (int e = t; e < NN * 3; e += THREADS) sm->xs[e] = x[b * NN * 3 + e];
    for (int e = t; e < NN; e += THREADS) sm->slotmap[e] = -1;
    if (t == 0) { sm->xsum[0] = 0.f; sm->xsum[1] = 0.f; sm->xsum[2] = 0.f; }
    const float c1bf = c1b[0] * c1s[0] + c1t[0];
    __syncthreads();

    const float xi0 = sm->xs[i * 3 + 0];
    const float xi1 = sm->xs[i * 3 + 1];
    const float xi2 = sm->xs[i * 3 + 2];

    // ---- distances ----
    for (int j = t; j < NN; j += THREADS) {
        const float dx = sm->xs[j * 3 + 0] - xi0;
        const float dy = sm->xs[j * 3 + 1] - xi1;
        const float dz = sm->xs[j * 3 + 2] - xi2;
        sm->d2all[j] = dx * dx + dy * dy + dz * dz;
    }
    __syncthreads();

    // ---- kNN: 16 sequential block argmins (tie-break lower index) ----
    const float INF = __int_as_float(0x7f800000);
    for (int s = 0; s < KNN; s++) {
        float bv = INF; int bidx = NN;
#pragma unroll
        for (int j = t; j < NN; j += THREADS) {
            const float v = sm->d2all[j];
            if (v < bv || (v == bv && j < bidx)) { bv = v; bidx = j; }
        }
#pragma unroll
        for (int off = 16; off; off >>= 1) {
            const float ov = __shfl_down_sync(0xffffffffu, bv, off);
            const int   oi = __shfl_down_sync(0xffffffffu, bidx, off);
            if (ov < bv || (ov == bv && oi < bidx)) { bv = ov; bidx = oi; }
        }
        if (lane == 0) { sm->redv[w] = bv; sm->redi[w] = bidx; }
        __syncthreads();
        if (t == 0) {
            float fv = sm->redv[0]; int fi = sm->redi[0];
#pragma unroll
            for (int q = 1; q < 8; q++) {
                const float wv = sm->redv[q]; const int wi = sm->redi[q];
                if (wv < fv || (wv == fv && wi < fi)) { fv = wv; fi = wi; }
            }
            sm->seli[s] = fi;
            sm->selval[s] = fv;
            sm->d2all[fi] = INF;
        }
        __syncthreads();
    }
    if (t < KNN) {
        sm->d2all[sm->seli[t]] = sm->selval[t];   // restore
        sm->slotmap[sm->seli[t]] = t;
    }
    __syncthreads();

    // ---- barrier-free mainloop ----
    float xacc0 = 0.f, xacc1 = 0.f, xacc2 = 0.f;
    const float* As_b = g_As + (size_t)(b * NN) * DMC;

    for (int tile = 0; tile < NTILES; tile++) {
        const int j0 = tile * TJ;
        const int r0 = j0 + w * 16 + g;
        const int r1 = r0 + 8;
        const float d2a = sm->d2all[r0];
        const float d2b = sm->d2all[r1];
        const float* A0 = As_b + r0 * DMC;
        const float* A1 = As_b + r1 * DMC;

        // build A1-fragments in registers: f1 = relu(As + Bsi + d2*wds)
        u32 ah[16], al[16];
#pragma unroll
        for (int ks = 0; ks < 4; ks++) {
            const int k0 = ks * 16 + 2 * tg;
            const float2 bs0 = *reinterpret_cast<const float2*>(&sm->Bsi[k0]);
            const float2 bs1 = *reinterpret_cast<const float2*>(&sm->Bsi[k0 + 8]);
            const float2 wd0 = *reinterpret_cast<const float2*>(&sm->wds[k0]);
            const float2 wd1 = *reinterpret_cast<const float2*>(&sm->wds[k0 + 8]);
            const float2 p0 = *reinterpret_cast<const float2*>(&A0[k0]);
            const float2 q0 = *reinterpret_cast<const float2*>(&A0[k0 + 8]);
            const float2 p1 = *reinterpret_cast<const float2*>(&A1[k0]);
            const float2 q1 = *reinterpret_cast<const float2*>(&A1[k0 + 8]);
            float v0 = fmaxf(fmaf(d2a, wd0.x, p0.x + bs0.x), 0.f);
            float v1 = fmaxf(fmaf(d2a, wd0.y, p0.y + bs0.y), 0.f);
            splitpair(v0, v1, ah[ks * 4 + 0], al[ks * 4 + 0]);      // row r0, k0..k0+1
            v0 = fmaxf(fmaf(d2b, wd0.x, p1.x + bs0.x), 0.f);
            v1 = fmaxf(fmaf(d2b, wd0.y, p1.y + bs0.y), 0.f);
            splitpair(v0, v1, ah[ks * 4 + 1], al[ks * 4 + 1]);      // row r1, k0..k0+1
            v0 = fmaxf(fmaf(d2a, wd1.x, q0.x + bs1.x), 0.f);
            v1 = fmaxf(fmaf(d2a, wd1.y, q0.y + bs1.y), 0.f);
            splitpair(v0, v1, ah[ks * 4 + 2], al[ks * 4 + 2]);      // row r0, k0+8..k0+9
            v0 = fmaxf(fmaf(d2b, wd1.x, q1.x + bs1.x), 0.f);
            v1 = fmaxf(fmaf(d2b, wd1.y, q1.y + bs1.y), 0.f);
            splitpair(v0, v1, ah[ks * 4 + 3], al[ks * 4 + 3]);      // row r1, k0+8..k0+9
        }

        // GEMM 1: acc = f1 @ W1fold  (bf16 3-term split)
        float acc[32];
#pragma unroll
        for (int q = 0; q < 32; q++) acc[q] = 0.f;
#pragma unroll
        for (int ks = 0; ks < 4; ks++) {
#pragma unroll
            for (int nt = 0; nt < 8; nt++) {
                const u64 bh = sm->B1h[ks * 256 + nt * 32 + lane];
                const u64 bl = sm->B1l[ks * 256 + nt * 32 + lane];
                const u32 bh0 = (u32)bh, bh1 = (u32)(bh >> 32);
                const u32 bl0 = (u32)bl, bl1 = (u32)(bl >> 32);
                mma16816(acc + nt * 4, ah + ks * 4, bh0, bh1);
                mma16816(acc + nt * 4, al + ks * 4, bh0, bh1);
                mma16816(acc + nt * 4, ah + ks * 4, bl0, bl1);
            }
        }

        // epilogue 1: f2 = relu(acc + bias1); stage selected rows; acc -> A2 frags
        const int slot0 = sm->slotmap[r0];
        const int slot1 = sm->slotmap[r1];
#pragma unroll
        for (int nt = 0; nt < 8; nt++) {
            const int n0 = nt * 8 + 2 * tg;
            const float2 bb = *reinterpret_cast<const float2*>(&sm->bias1[n0]);
            const float v0 = fmaxf(acc[nt * 4 + 0] + bb.x, 0.f);
            const float v1 = fmaxf(acc[nt * 4 + 1] + bb.y, 0.f);
            const float v2 = fmaxf(acc[nt * 4 + 2] + bb.x, 0.f);
            const float v3 = fmaxf(acc[nt * 4 + 3] + bb.y, 0.f);
            if (slot0 >= 0)
                *reinterpret_cast<float2*>(&sm->stage[slot0][n0]) = make_float2(v0, v1);
            if (slot1 >= 0)
                *reinterpret_cast<float2*>(&sm->stage[slot1][n0]) = make_float2(v2, v3);
            const int ks2 = nt >> 1, hh = (nt & 1) * 2;
            splitpair(v0, v1, ah[ks2 * 4 + hh + 0], al[ks2 * 4 + hh + 0]);
            splitpair(v2, v3, ah[ks2 * 4 + hh + 1], al[ks2 * 4 + hh + 1]);
        }

        // GEMM 2: acc = f2 @ W2fold
#pragma unroll
        for (int q = 0; q < 32; q++) acc[q] = 0.f;
#pragma unroll
        for (int ks = 0; ks < 4; ks++) {
#pragma unroll
            for (int nt = 0; nt < 8; nt++) {
                const u64 bh = sm->B2h[ks * 256 + nt * 32 + lane];
                const u64 bl = sm->B2l[ks * 256 + nt * 32 + lane];
                const u32 bh0 = (u32)bh, bh1 = (u32)(bh >> 32);
                const u32 bl0 = (u32)bl, bl1 = (u32)(bl >> 32);
                mma16816(acc + nt * 4, ah + ks * 4, bh0, bh1);
                mma16816(acc + nt * 4, al + ks * 4, bh0, bh1);
                mma16816(acc + nt * 4, ah + ks * 4, bl0, bl1);
            }
        }

        // epilogue 2: g = relu(acc + bias2); c1 dot; coordinate accumulation
        float dot0 = 0.f, dot1 = 0.f;
#pragma unroll
        for (int nt = 0; nt < 8; nt++) {
            const int n0 = nt * 8 + 2 * tg;
            const float2 bb = *reinterpret_cast<const float2*>(&sm->bias2[n0]);
            const float2 cw = *reinterpret_cast<const float2*>(&sm->c1wf[n0]);
            const float v0 = fmaxf(acc[nt * 4 + 0] + bb.x, 0.f);
            const float v1 = fmaxf(acc[nt * 4 + 1] + bb.y, 0.f);
            const float v2 = fmaxf(acc[nt * 4 + 2] + bb.x, 0.f);
            const float v3 = fmaxf(acc[nt * 4 + 3] + bb.y, 0.f);
            dot0 = fmaf(v0, cw.x, fmaf(v1, cw.y, dot0));
            dot1 = fmaf(v2, cw.x, fmaf(v3, cw.y, dot1));
        }
        dot0 += __shfl_xor_sync(0xffffffffu, dot0, 1);
        dot0 += __shfl_xor_sync(0xffffffffu, dot0, 2);
        dot1 += __shfl_xor_sync(0xffffffffu, dot1, 1);
        dot1 += __shfl_xor_sync(0xffffffffu, dot1, 2);
        if (tg == 0) {
            const float w0 = fmaxf(dot0 + c1bf, 0.f);
            const float w1 = fmaxf(dot1 + c1bf, 0.f);
            xacc0 += w0 * (sm->xs[r0 * 3 + 0] - xi0) + w1 * (sm->xs[r1 * 3 + 0] - xi0);
            xacc1 += w0 * (sm->xs[r0 * 3 + 1] - xi1) + w1 * (sm->xs[r1 * 3 + 1] - xi1);
            xacc2 += w0 * (sm->xs[r0 * 3 + 2] - xi2) + w1 * (sm->xs[r1 * 3 + 2] - xi2);
        }
    }

    // ---- reduce coordinate update ----
#pragma unroll
    for (int off = 16; off; off >>= 1) {
        xacc0 += __shfl_down_sync(0xffffffffu, xacc0, off);
        xacc1 += __shfl_down_sync(0xffffffffu, xacc1, off);
        xacc2 += __shfl_down_sync(0xffffffffu, xacc2, off);
    }
    if (lane == 0) {
        atomicAdd(&sm->xsum[0], xacc0);
        atomicAdd(&sm->xsum[1], xacc1);
        atomicAdd(&sm->xsum[2], xacc2);
    }
    __syncthreads();   // stage + xsum complete

    // ---- m_node from staged rows ----
    if (t < DMC) {
        float m = 0.f;
#pragma unroll
        for (int s = 0; s < KNN; s++) m += sm->stage[s][t];
        sm->mnode[t] = m;
    }
    __syncthreads();

    // ---- outputs ----
    if (t < 3) out[bi * 3 + t] = sm->xs[i * 3 + t] + sm->xsum[t];
    if (t < DD) {
        float acc = 0.f;
        const float* hrow = h + bi * DD;
#pragma unroll
        for (int k = 0; k < DD; k++) acc = fmaf(hrow[k], n0W[k * DD + t], acc);
#pragma unroll
        for (int k = 0; k < DMC; k++) acc = fmaf(sm->mnode[k], n0W[(DD + k) * DD + t], acc);
        const float v = (acc + n0b[t]) * n0s[t] + n0t[t];
        out[NB * NN * 3 + bi * DD + t] = fmaxf(v, 0.f);
    }
}

// ---------------------------------------------------------------------------
extern "C" void kernel_launch(void* const* d_in, const int* in_sizes, int n_in,
                              void* d_out, int out_size) {
    const float* x   = (const float*)d_in[0];
    const float* h   = (const float*)d_in[1];
    const float* e0W = (const float*)d_in[2];
    const float* e0b = (const float*)d_in[3];
    const float* e0s = (const float*)d_in[4];
    const float* e0t = (const float*)d_in[5];
    const float* e1W = (const float*)d_in[6];
    const float* e1b = (const float*)d_in[7];
    const float* e1s = (const float*)d_in[8];
    const float* e1t = (const float*)d_in[9];
    const float* c0W = (const float*)d_in[10];
    const float* c0b = (const float*)d_in[11];
    const float* c0s = (const float*)d_in[12];
    const float* c0t = (const float*)d_in[13];
    const float* c1W = (const float*)d_in[14];
    const float* c1b = (const float*)d_in[15];
    const float* c1s = (const float*)d_in[16];
    const float* c1t = (const float*)d_in[17];
    const float* n0W = (const float*)d_in[18];
    const float* n0b = (const float*)d_in[19];
    const float* n0s = (const float*)d_in[20];
    const float* n0t = (const float*)d_in[21];
    float* out = (float*)d_out;

    static_assert(sizeof(SmemLayout) < 100 * 1024, "smem too big");
    cudaFuncSetAttribute(egnn_main_kernel,
                         cudaFuncAttributeMaxDynamicSharedMemorySize,
                         (int)sizeof(SmemLayout));

    precompute_kernel<<<NB * NN, 64>>>(h, e0W, e0b, e0s, e0t);
    egnn_main_kernel<<<NB * NN, THREADS, sizeof(SmemLayout)>>>(
        x, h, e0W, e0s,
        e1W, e1b, e1s, e1t,
        c0W, c0b, c0s, c0t,
        c1W, c1b, c1s, c1t,
        n0W, n0b, n0s, n0t,
        out);
}